// round 12
// baseline (speedup 1.0000x reference)
#include <cuda_runtime.h>
#include <cuda_bf16.h>
#include <cstdint>

#define Bdim 4
#define Sdim 2048
#define Edim 1024
#define Hdim 16
#define Ddim 64
#define Mrows 8192          // B*S
#define BHdim 64            // B*H
#define KDIM 1024
#define NCHUNK 16           // KDIM / 64
#define QKVN 3072

// tcgen05 is arch-SPECIFIC: only available in 'a'-suffixed device passes.
#if defined(__CUDA_ARCH__) && (defined(__CUDA_ARCH_FEAT_SM103_ALL) || \
    defined(__CUDA_ARCH_FEAT_SM100_ALL) || defined(__CUDA_ARCH_FEAT_SM101_ALL) || \
    defined(__CUDA_ARCH_SPECIFIC__))
#define HAS_TCGEN05 1
#else
#define HAS_TCGEN05 0
#endif

// ---------------- scratch (device globals; no allocs allowed) ----------------
__device__ __nv_bfloat16 g_xhi[Mrows * KDIM];
__device__ __nv_bfloat16 g_xlo[Mrows * KDIM];
__device__ __nv_bfloat16 g_wt_hi[QKVN * KDIM];
__device__ __nv_bfloat16 g_wt_lo[QKVN * KDIM];
__device__ __nv_bfloat16 g_wp_hi[Edim * KDIM];
__device__ __nv_bfloat16 g_wp_lo[Edim * KDIM];
__device__ __nv_bfloat16 g_ahi[Mrows * KDIM];
__device__ __nv_bfloat16 g_alo[Mrows * KDIM];
__device__ __nv_bfloat16 g_qhi[BHdim * Sdim * Ddim];
__device__ __nv_bfloat16 g_qlo[BHdim * Sdim * Ddim];
__device__ __nv_bfloat16 g_khi[BHdim * Sdim * Ddim];
__device__ __nv_bfloat16 g_klo[BHdim * Sdim * Ddim];
__device__ __nv_bfloat16 g_vThi[BHdim * Ddim * Sdim];
__device__ __nv_bfloat16 g_vTlo[BHdim * Ddim * Sdim];

// ---------------- PTX helpers ----------------
__device__ __forceinline__ uint32_t elect_one_pred() {
    uint32_t pred;
    asm volatile("{\n\t.reg .pred p;\n\telect.sync _|p, 0xFFFFFFFF;\n\t"
                 "selp.b32 %0, 1, 0, p;\n\t}" : "=r"(pred));
    return pred;
}
__device__ __forceinline__ uint32_t smem_to_u32(const void* p) {
    uint32_t a;
    asm("{ .reg .u64 t; cvta.to.shared.u64 t, %1; cvt.u32.u64 %0, t; }" : "=r"(a) : "l"(p));
    return a;
}
#define MBARRIER_INIT(addr, cnt) \
    asm volatile("mbarrier.init.shared.b64 [%0], %1;" :: "r"((uint32_t)(addr)), "r"((uint32_t)(cnt)) : "memory")
#define MBARRIER_ARRIVE(addr) \
    asm volatile("mbarrier.arrive.shared.b64 _, [%0];" :: "r"((uint32_t)(addr)) : "memory")
#define MBARRIER_WAIT_PARITY(mbar_smem_addr, phase_parity) do { \
    uint32_t _mbar = (uint32_t)(mbar_smem_addr); \
    uint32_t _parity = (uint32_t)(phase_parity); \
    uint32_t _done; \
    asm volatile("{\n\t.reg .pred p;\n\t" \
        "mbarrier.try_wait.parity.acquire.cta.shared::cta.b64 p, [%1], %2;\n\t" \
        "selp.b32 %0, 1, 0, p;\n\t}" : "=r"(_done) : "r"(_mbar), "r"(_parity) : "memory"); \
    if (!_done) { \
        asm volatile("{\n\t.reg .pred P1;\n\t" \
            "WAIT_LOOP_%=:\n\t" \
            "mbarrier.try_wait.parity.acquire.cta.shared::cta.b64 P1, [%0], %1, 0x989680;\n\t" \
            "@P1 bra.uni WAIT_DONE_%=;\n\t" \
            "bra.uni WAIT_LOOP_%=;\n\t" \
            "WAIT_DONE_%=:\n\t}" :: "r"(_mbar), "r"(_parity) : "memory"); \
    } \
} while (0)

#define CPA16(dst, src) \
    asm volatile("cp.async.cg.shared.global [%0], [%1], 16;" :: "r"((uint32_t)(dst)), "l"(src) : "memory")
#define CPA_COMMIT() asm volatile("cp.async.commit_group;" ::: "memory")
#define CPA_WAIT(n)  asm volatile("cp.async.wait_group %0;" :: "n"(n) : "memory")

#if HAS_TCGEN05
#define TCGEN05_ALLOC(smem_addr, n) \
    asm volatile("tcgen05.alloc.cta_group::1.sync.aligned.shared::cta.b32 [%0], %1;" \
                 :: "r"((uint32_t)(smem_addr)), "r"((uint32_t)(n)) : "memory")
#define TCGEN05_DEALLOC(tmem, n) \
    asm volatile("tcgen05.dealloc.cta_group::1.sync.aligned.b32 %0, %1;" :: "r"(tmem), "r"((uint32_t)(n)))
#define TCGEN05_RELINQ() \
    asm volatile("tcgen05.relinquish_alloc_permit.cta_group::1.sync.aligned;")
#define TCGEN05_COMMIT(mbar) \
    asm volatile("tcgen05.commit.cta_group::1.mbarrier::arrive::one.shared::cluster.b64 [%0];" \
                 :: "r"((uint32_t)(mbar)) : "memory")
#define TCGEN05_WAIT_LD() asm volatile("tcgen05.wait::ld.sync.aligned;" ::: "memory")
#define TCGEN05_WAIT_ST() asm volatile("tcgen05.wait::st.sync.aligned;" ::: "memory")
#define TCGEN05_FENCE_BEFORE() asm volatile("tcgen05.fence::before_thread_sync;" ::: "memory")
#define TCGEN05_FENCE_AFTER() asm volatile("tcgen05.fence::after_thread_sync;" ::: "memory")
#define FENCE_PROXY_ASYNC() asm volatile("fence.proxy.async.shared::cta;" ::: "memory")
#define TCGEN05_LD_X32(r, addr) \
    asm volatile("tcgen05.ld.sync.aligned.32x32b.x32.b32 " \
        "{%0, %1, %2, %3, %4, %5, %6, %7, %8, %9, %10, %11, %12, %13, %14, %15, " \
        "%16, %17, %18, %19, %20, %21, %22, %23, %24, %25, %26, %27, %28, %29, %30, %31}, [%32];" \
        : "=r"((r)[0]),  "=r"((r)[1]),  "=r"((r)[2]),  "=r"((r)[3]), \
          "=r"((r)[4]),  "=r"((r)[5]),  "=r"((r)[6]),  "=r"((r)[7]), \
          "=r"((r)[8]),  "=r"((r)[9]),  "=r"((r)[10]), "=r"((r)[11]), \
          "=r"((r)[12]), "=r"((r)[13]), "=r"((r)[14]), "=r"((r)[15]), \
          "=r"((r)[16]), "=r"((r)[17]), "=r"((r)[18]), "=r"((r)[19]), \
          "=r"((r)[20]), "=r"((r)[21]), "=r"((r)[22]), "=r"((r)[23]), \
          "=r"((r)[24]), "=r"((r)[25]), "=r"((r)[26]), "=r"((r)[27]), \
          "=r"((r)[28]), "=r"((r)[29]), "=r"((r)[30]), "=r"((r)[31]) \
        : "r"(addr))
#define TCGEN05_ST_X16(addr, r) \
    asm volatile("tcgen05.st.sync.aligned.32x32b.x16.b32 [%0], " \
        "{%1, %2, %3, %4, %5, %6, %7, %8, %9, %10, %11, %12, %13, %14, %15, %16};" \
        :: "r"(addr), \
           "r"((r)[0]),  "r"((r)[1]),  "r"((r)[2]),  "r"((r)[3]), \
           "r"((r)[4]),  "r"((r)[5]),  "r"((r)[6]),  "r"((r)[7]), \
           "r"((r)[8]),  "r"((r)[9]),  "r"((r)[10]), "r"((r)[11]), \
           "r"((r)[12]), "r"((r)[13]), "r"((r)[14]), "r"((r)[15]) \
        : "memory")
#endif  // HAS_TCGEN05

#define SMEM_SWIZZLE_128B(off) ((off) ^ (((off) >> 3) & 0x70))

static constexpr uint64_t SMEM_DESC_BASE_SW128 =
    (uint64_t(2) << 61) | (uint64_t(1) << 46) | (uint64_t(64) << 32) | (uint64_t(1) << 16);
#define MAKE_SMEM_DESC(base) (SMEM_DESC_BASE_SW128 | ((uint64_t)((base) >> 4) & 0x3FFF))

#define IDESC_N128 ((1u << 4) | (1u << 7) | (1u << 10) | ((128u / 8) << 17) | ((128u / 16) << 24))
#define IDESC_N64  ((1u << 4) | (1u << 7) | (1u << 10) | ((64u  / 8) << 17) | ((128u / 16) << 24))

#if HAS_TCGEN05
__device__ __forceinline__ void mma_f16_ss(uint32_t d_tmem, uint64_t a_desc,
                                           uint64_t b_desc, uint32_t idesc, bool acc) {
    uint32_t en = acc ? 1u : 0u;
    asm volatile("{\n\t.reg .pred p;\n\tsetp.ne.u32 p, %5, 0;\n\t"
        "tcgen05.mma.cta_group::1.kind::f16 [%0], %1, %2, %3, {%4, %4, %4, %4}, p;\n\t}"
        :: "r"(d_tmem), "l"(a_desc), "l"(b_desc), "r"(idesc), "r"(0u), "r"(en)
        : "memory");
}
__device__ __forceinline__ void mma_f16_ts(uint32_t d_tmem, uint32_t a_tmem,
                                           uint64_t b_desc, uint32_t idesc, bool acc) {
    uint32_t en = acc ? 1u : 0u;
    asm volatile("{\n\t.reg .pred p;\n\tsetp.ne.u32 p, %5, 0;\n\t"
        "tcgen05.mma.cta_group::1.kind::f16 [%0], [%1], %2, %3, {%4, %4, %4, %4}, p;\n\t}"
        :: "r"(d_tmem), "r"(a_tmem), "l"(b_desc), "r"(idesc), "r"(0u), "r"(en)
        : "memory");
}
#endif

__device__ __forceinline__ void split2(float v, __nv_bfloat16& h, __nv_bfloat16& l) {
    h = __float2bfloat16(v);
    l = __float2bfloat16(v - __bfloat162float(h));
}

// ============ GEMM smem: 2 stages of 96KB (M=128, N=256 tile, K-chunk 64) ====
#define GS_SZ 98304
#define G_MBAR_L 196608
#define G_MBAR_M 196616
#define G_MBAR_F 196624
#define G_TMPTR  196632
#define G_SMEM_BYTES 196736
#define EPI_STRIDE 133

// ============ attention smem (dual q-tile) ============
// QA hi@0, QA lo@16384, QB hi@32768, QB lo@49152; 2 KV stages @65536 + s*65536
// stage: Kh+0, Kl+16384, VTh+32768 (two 8K blocks), VTl+49152
#define AQ_BASE 0
#define AKV_BASE 65536
#define AKV_SZ 65536
#define A_MB_QKA 196608
#define A_MB_QKB 196616
#define A_MB_PVA 196624
#define A_MB_PVB 196632
#define A_TMPTR  196640
#define A_SMEM_BYTES 196736

// ---------------- split conversion kernels ----------------
__global__ __launch_bounds__(256) void conv_split(
    const float* __restrict__ src, __nv_bfloat16* __restrict__ hi,
    __nv_bfloat16* __restrict__ lo, int n4)
{
    int i = blockIdx.x * 256 + threadIdx.x;
    if (i >= n4) return;
    float4 v = ((const float4*)src)[i];
    __nv_bfloat16 h0, h1, h2, h3, l0, l1, l2, l3;
    split2(v.x, h0, l0); split2(v.y, h1, l1);
    split2(v.z, h2, l2); split2(v.w, h3, l3);
    ((ushort4*)hi)[i] = make_ushort4(__bfloat16_as_ushort(h0), __bfloat16_as_ushort(h1),
                                     __bfloat16_as_ushort(h2), __bfloat16_as_ushort(h3));
    ((ushort4*)lo)[i] = make_ushort4(__bfloat16_as_ushort(l0), __bfloat16_as_ushort(l1),
                                     __bfloat16_as_ushort(l2), __bfloat16_as_ushort(l3));
}

__global__ __launch_bounds__(256) void conv_wt(
    const float* __restrict__ Wq, const float* __restrict__ Wk,
    const float* __restrict__ Wv)
{
    __shared__ float tile[64][65];
    const int tid = threadIdx.x;
    const int e0 = blockIdx.x * 64;
    const int h  = blockIdx.y;
    const int sel = blockIdx.z;
    const float* __restrict__ W = (sel == 0) ? Wq : (sel == 1) ? Wk : Wv;
    #pragma unroll
    for (int i = tid; i < 64 * 64; i += 256) {
        int r = i >> 6, d = i & 63;
        tile[r][d] = W[((size_t)h * Edim + e0 + r) * Ddim + d];
    }
    __syncthreads();
    const int nbase = sel * 1024 + h * 64;
    #pragma unroll
    for (int i = tid; i < 64 * 64; i += 256) {
        int d = i >> 6, r = i & 63;
        __nv_bfloat16 hv, lv;
        split2(tile[r][d], hv, lv);
        size_t idx = (size_t)(nbase + d) * KDIM + e0 + r;
        g_wt_hi[idx] = hv;
        g_wt_lo[idx] = lv;
    }
}

__global__ __launch_bounds__(256) void conv_wp(const float* __restrict__ Wp)
{
    __shared__ float tile[64][65];
    const int tid = threadIdx.x;
    const int k0 = blockIdx.x * 64;
    const int n0 = blockIdx.y * 64;
    #pragma unroll
    for (int i = tid; i < 64 * 64; i += 256) {
        int r = i >> 6, c = i & 63;
        tile[r][c] = Wp[(size_t)(k0 + r) * Edim + n0 + c];
    }
    __syncthreads();
    #pragma unroll
    for (int i = tid; i < 64 * 64; i += 256) {
        int c = i >> 6, r = i & 63;
        __nv_bfloat16 hv, lv;
        split2(tile[r][c], hv, lv);
        size_t idx = (size_t)(n0 + c) * KDIM + k0 + r;
        g_wp_hi[idx] = hv;
        g_wp_lo[idx] = lv;
    }
}

// ---------------- GEMM chunk load by 96 loader threads ----------------
__device__ __forceinline__ void ld_chunk256_ws(
    const __nv_bfloat16* __restrict__ Ah, const __nv_bfloat16* __restrict__ Al,
    const __nv_bfloat16* __restrict__ Bh, const __nv_bfloat16* __restrict__ Bl,
    int m0, int n0, int k0, uint32_t sbuf, int lt)
{
    #pragma unroll
    for (int u = 0; u < 11; u++) {
        int idx = lt + u * 96;
        if (idx < 1024) {
            int r = idx >> 3, g = idx & 7;
            uint32_t sw = SMEM_SWIZZLE_128B((uint32_t)(r * 128 + g * 16));
            size_t ga = (size_t)(m0 + r) * KDIM + k0 + g * 8;
            CPA16(sbuf + 0     + sw, Ah + ga);
            CPA16(sbuf + 16384 + sw, Al + ga);
        }
    }
    #pragma unroll
    for (int u = 0; u < 22; u++) {
        int idx = lt + u * 96;
        if (idx < 2048) {
            int r = idx >> 3, g = idx & 7;
            uint32_t sw = SMEM_SWIZZLE_128B((uint32_t)(r * 128 + g * 16));
            size_t gb = (size_t)(n0 + r) * KDIM + k0 + g * 8;
            CPA16(sbuf + 32768 + sw, Bh + gb);
            CPA16(sbuf + 65536 + sw, Bl + gb);
        }
    }
    CPA_COMMIT();
}

#if HAS_TCGEN05
// ---------------- warp-specialized pipelined GEMM mainloop ------------------
__device__ __forceinline__ void tc_mainloop(
    const __nv_bfloat16* __restrict__ Ah, const __nv_bfloat16* __restrict__ Al,
    const __nv_bfloat16* __restrict__ Bh, const __nv_bfloat16* __restrict__ Bl,
    int m0, int n0, uint32_t su, uint32_t tmem_d, int tid, int wid)
{
    if (wid == 0) {
        for (int ch = 0; ch < NCHUNK; ch++) {
            MBARRIER_WAIT_PARITY(su + G_MBAR_L, ch & 1);
            if (elect_one_pred()) {
                uint32_t sb = su + (uint32_t)(ch & 1) * GS_SZ;
                uint64_t dAh  = MAKE_SMEM_DESC(sb);
                uint64_t dAl  = MAKE_SMEM_DESC(sb + 16384);
                uint64_t dBh0 = MAKE_SMEM_DESC(sb + 32768);
                uint64_t dBh1 = MAKE_SMEM_DESC(sb + 49152);
                uint64_t dBl0 = MAKE_SMEM_DESC(sb + 65536);
                uint64_t dBl1 = MAKE_SMEM_DESC(sb + 81920);
                #pragma unroll
                for (int ks = 0; ks < 4; ks++) {
                    uint64_t o = (uint64_t)(ks * 2);
                    bool first = (ch == 0 && ks == 0);
                    mma_f16_ss(tmem_d,       dAh + o, dBh0 + o, IDESC_N128, !first);
                    mma_f16_ss(tmem_d,       dAh + o, dBl0 + o, IDESC_N128, true);
                    mma_f16_ss(tmem_d,       dAl + o, dBh0 + o, IDESC_N128, true);
                    mma_f16_ss(tmem_d + 128, dAh + o, dBh1 + o, IDESC_N128, !first);
                    mma_f16_ss(tmem_d + 128, dAh + o, dBl1 + o, IDESC_N128, true);
                    mma_f16_ss(tmem_d + 128, dAl + o, dBh1 + o, IDESC_N128, true);
                }
                TCGEN05_COMMIT(su + G_MBAR_M);
                if (ch == NCHUNK - 1) TCGEN05_COMMIT(su + G_MBAR_F);
            }
        }
    } else {
        const int lt = tid - 32;
        const bool lane0 = ((tid & 31) == 0);
        ld_chunk256_ws(Ah, Al, Bh, Bl, m0, n0, 0,  su,         lt);
        ld_chunk256_ws(Ah, Al, Bh, Bl, m0, n0, 64, su + GS_SZ, lt);
        CPA_WAIT(1);
        FENCE_PROXY_ASYNC();
        __syncwarp();
        if (lane0) MBARRIER_ARRIVE(su + G_MBAR_L);
        for (int ch = 0; ch < NCHUNK; ch++) {
            if (ch + 1 < NCHUNK) {
                CPA_WAIT(0);
                FENCE_PROXY_ASYNC();
                __syncwarp();
                if (lane0) MBARRIER_ARRIVE(su + G_MBAR_L);
            }
            if (ch + 2 < NCHUNK) {
                MBARRIER_WAIT_PARITY(su + G_MBAR_M, ch & 1);
                ld_chunk256_ws(Ah, Al, Bh, Bl, m0, n0, (ch + 2) << 6,
                               su + (uint32_t)(ch & 1) * GS_SZ, lt);
            }
        }
    }
    __syncthreads();
    MBARRIER_WAIT_PARITY(su + G_MBAR_F, 0);
}

__device__ __forceinline__ void epi_to_smem(char* smem, uint32_t tmem_d, int tid)
{
    #pragma unroll
    for (int cb = 0; cb < 8; cb++) {
        uint32_t dreg[32];
        TCGEN05_LD_X32(dreg, tmem_d + cb * 32);
        TCGEN05_WAIT_LD();
        #pragma unroll
        for (int j = 0; j < 32; j++) {
            int c = cb * 32 + j;
            *(float*)(smem + (((size_t)c * EPI_STRIDE + tid) << 2)) = __uint_as_float(dreg[j]);
        }
    }
    __syncthreads();
}
#endif  // HAS_TCGEN05

// ---------------- kernel: fused QKV projection (tile 128m x 256n) ----------
__global__ __launch_bounds__(128) void qkv_tc()
{
    extern __shared__ char smem[];
    const int tid = threadIdx.x;
    const int n0 = blockIdx.x * 256;
    const int m0 = blockIdx.y * 128;
    const int sel = n0 >> 10;

#if HAS_TCGEN05
    const uint32_t su = smem_to_u32(smem);
    const int wid = tid >> 5;

    if (wid == 0) { TCGEN05_ALLOC(su + G_TMPTR, 256); TCGEN05_RELINQ(); }
    if (tid == 0) {
        MBARRIER_INIT(su + G_MBAR_L, 3);
        MBARRIER_INIT(su + G_MBAR_M, 1);
        MBARRIER_INIT(su + G_MBAR_F, 1);
    }
    __syncthreads();
    uint32_t tmem;
    asm volatile("ld.shared.b32 %0, [%1];" : "=r"(tmem) : "r"(su + G_TMPTR));

    tc_mainloop(g_xhi, g_xlo, g_wt_hi, g_wt_lo, m0, n0, su, tmem, tid, wid);

    TCGEN05_FENCE_AFTER();
    epi_to_smem(smem, tmem, tid);

    const int bb = m0 >> 11;
    const int s0c = m0 & 2047;
    if (sel < 2) {
        __nv_bfloat16* __restrict__ hiA = sel ? g_khi : g_qhi;
        __nv_bfloat16* __restrict__ loA = sel ? g_klo : g_qlo;
        const int cl = tid & 7;
        const int rr = tid >> 3;
        #pragma unroll
        for (int rep = 0; rep < 8; rep++) {
            int m = rr + rep * 16;
            int ss = s0c + m;
            #pragma unroll
            for (int q = 0; q < 8; q++) {
                int c = (cl + q * 8) * 4;
                float v0 = *(const float*)(smem + (((size_t)(c + 0) * EPI_STRIDE + m) << 2));
                float v1 = *(const float*)(smem + (((size_t)(c + 1) * EPI_STRIDE + m) << 2));
                float v2 = *(const float*)(smem + (((size_t)(c + 2) * EPI_STRIDE + m) << 2));
                float v3 = *(const float*)(smem + (((size_t)(c + 3) * EPI_STRIDE + m) << 2));
                int n = n0 + c;
                int h = (n >> 6) & 15;
                int d = n & 63;
                size_t idx = ((size_t)(bb * Hdim + h) * Sdim + ss) * Ddim + d;
                __nv_bfloat16 h0, h1, h2, h3, l0, l1, l2, l3;
                split2(v0, h0, l0); split2(v1, h1, l1);
                split2(v2, h2, l2); split2(v3, h3, l3);
                *(ushort4*)(hiA + idx) = make_ushort4(
                    __bfloat16_as_ushort(h0), __bfloat16_as_ushort(h1),
                    __bfloat16_as_ushort(h2), __bfloat16_as_ushort(h3));
                *(ushort4*)(loA + idx) = make_ushort4(
                    __bfloat16_as_ushort(l0), __bfloat16_as_ushort(l1),
                    __bfloat16_as_ushort(l2), __bfloat16_as_ushort(l3));
            }
        }
    } else {
        #pragma unroll
        for (int half = 0; half < 2; half++) {
            int c = tid + half * 128;
            int n = n0 + c;
            int h = (n >> 6) & 15;
            int d = n & 63;
            size_t rowb = ((size_t)(bb * Hdim + h) * Ddim + d) * Sdim + s0c;
            const float* col = (const float*)(smem) + (size_t)c * EPI_STRIDE;
            #pragma unroll 4
            for (int mq = 0; mq < 32; mq++) {
                float v0 = col[mq * 4 + 0], v1 = col[mq * 4 + 1];
                float v2 = col[mq * 4 + 2], v3 = col[mq * 4 + 3];
                __nv_bfloat16 h0, h1, h2, h3, l0, l1, l2, l3;
                split2(v0, h0, l0); split2(v1, h1, l1);
                split2(v2, h2, l2); split2(v3, h3, l3);
                *(ushort4*)(g_vThi + rowb + mq * 4) = make_ushort4(
                    __bfloat16_as_ushort(h0), __bfloat16_as_ushort(h1),
                    __bfloat16_as_ushort(h2), __bfloat16_as_ushort(h3));
                *(ushort4*)(g_vTlo + rowb + mq * 4) = make_ushort4(
                    __bfloat16_as_ushort(l0), __bfloat16_as_ushort(l1),
                    __bfloat16_as_ushort(l2), __bfloat16_as_ushort(l3));
            }
        }
    }

    __syncthreads();
    if (wid == 0) TCGEN05_DEALLOC(tmem, 256);
#else
    (void)smem;
    const int m = m0 + tid;
    const int bb = m >> 11, ss = m & 2047;
    for (int nc = 0; nc < 256; nc++) {
        const int n = n0 + nc;
        float s = 0.f;
        for (int k = 0; k < KDIM; k++) {
            float a = __bfloat162float(g_xhi[(size_t)m * KDIM + k]) +
                      __bfloat162float(g_xlo[(size_t)m * KDIM + k]);
            s += a * (__bfloat162float(g_wt_hi[(size_t)n * KDIM + k]) +
                      __bfloat162float(g_wt_lo[(size_t)n * KDIM + k]));
        }
        int rn = n & 1023;
        int h = rn >> 6, d = rn & 63;
        __nv_bfloat16 hv, lv;
        split2(s, hv, lv);
        if (sel < 2) {
            size_t idx = ((size_t)(bb * Hdim + h) * Sdim + ss) * Ddim + d;
            (sel ? g_khi : g_qhi)[idx] = hv;
            (sel ? g_klo : g_qlo)[idx] = lv;
        } else {
            size_t idx = ((size_t)(bb * Hdim + h) * Ddim + d) * Sdim + ss;
            g_vThi[idx] = hv;
            g_vTlo[idx] = lv;
        }
    }
#endif
}

#if HAS_TCGEN05
// cp.async one KV stage (K 128x64 hi/lo + V^T 64x128 hi/lo as two 64x64 blocks)
__device__ __forceinline__ void attn_ld_kv(int bh, int j0, uint32_t sb_u, int tid)
{
    #pragma unroll
    for (int u = 0; u < 4; u++) {
        int idx = tid + u * 256;
        int r = idx >> 3, g = idx & 7;
        uint32_t sw = SMEM_SWIZZLE_128B((uint32_t)(r * 128 + g * 16));
        size_t kb = ((size_t)bh * Sdim + j0 + r) * Ddim + g * 8;
        CPA16(sb_u + 0     + sw, g_khi + kb);
        CPA16(sb_u + 16384 + sw, g_klo + kb);
    }
    #pragma unroll
    for (int u = 0; u < 4; u++) {
        int idx = tid + u * 256;
        int d = idx >> 4, gg = idx & 15;
        int kb2 = gg >> 3, gi = gg & 7;
        uint32_t sw = SMEM_SWIZZLE_128B((uint32_t)(d * 128 + gi * 16));
        size_t vb = ((size_t)bh * Ddim + d) * Sdim + j0 + kb2 * 64 + gi * 8;
        CPA16(sb_u + 32768 + kb2 * 8192 + sw, g_vThi + vb);
        CPA16(sb_u + 49152 + kb2 * 8192 + sw, g_vTlo + vb);
    }
    CPA_COMMIT();
}

// issue QK tile: S(region) = Q * K^T (hi/lo, 12 dispatches), commit to mbar
__device__ __forceinline__ void issue_qk(uint32_t region, uint64_t qh, uint64_t ql,
                                         uint32_t sb, uint32_t mbar)
{
    uint64_t dKh = MAKE_SMEM_DESC(sb);
    uint64_t dKl = MAKE_SMEM_DESC(sb + 16384);
    #pragma unroll
    for (int ks = 0; ks < 4; ks++) {
        uint64_t o = (uint64_t)(ks * 2);
        mma_f16_ss(region, qh + o, dKh + o, IDESC_N128, ks != 0);
        mma_f16_ss(region, qh + o, dKl + o, IDESC_N128, true);
        mma_f16_ss(region, ql + o, dKh + o, IDESC_N128, true);
    }
    TCGEN05_COMMIT(mbar);
}

// issue PV tile: O(tO) += P(region) * V (hi/lo, 24 dispatches), commit
__device__ __forceinline__ void issue_pv(uint32_t tO, uint32_t region, uint32_t sb,
                                         bool firstj, uint32_t mbar)
{
    uint64_t dVh0 = MAKE_SMEM_DESC(sb + 32768);
    uint64_t dVh1 = MAKE_SMEM_DESC(sb + 32768 + 8192);
    uint64_t dVl0 = MAKE_SMEM_DESC(sb + 49152);
    uint64_t dVl1 = MAKE_SMEM_DESC(sb + 49152 + 8192);
    #pragma unroll
    for (int ks = 0; ks < 8; ks++) {
        uint64_t vh = (ks < 4 ? dVh0 : dVh1) + (uint64_t)((ks & 3) * 2);
        uint64_t vl = (ks < 4 ? dVl0 : dVl1) + (uint64_t)((ks & 3) * 2);
        uint32_t aH = region + ks * 8;
        uint32_t aL = region + 64 + ks * 8;
        mma_f16_ts(tO, aH, vh, IDESC_N64, !(firstj && ks == 0));
        mma_f16_ts(tO, aH, vl, IDESC_N64, true);
        mma_f16_ts(tO, aL, vh, IDESC_N64, true);
    }
    TCGEN05_COMMIT(mbar);
}

// softmax of one tile's S region: exp + mask + pack + STTM P in place.
// Called by ALL 256 threads (contains __syncthreads).
__device__ __forceinline__ void softmax_tile(uint32_t region, int j0, int qrow,
                                             int wg, int sub, float& lsum)
{
    TCGEN05_FENCE_AFTER();
    uint32_t pk[4][16];
    #pragma unroll
    for (int cb2 = 0; cb2 < 2; cb2++) {
        uint32_t sr[32];
        TCGEN05_LD_X32(sr, region + wg * 64 + cb2 * 32);
        TCGEN05_WAIT_LD();
        #pragma unroll
        for (int c2 = 0; c2 < 16; c2++) {
            int key0 = j0 + wg * 64 + cb2 * 32 + 2 * c2;
            float s0 = __uint_as_float(sr[2 * c2])     * 0.125f;
            float s1 = __uint_as_float(sr[2 * c2 + 1]) * 0.125f;
            float p0 = (key0     <= qrow) ? __expf(s0) : 0.0f;
            float p1 = (key0 + 1 <= qrow) ? __expf(s1) : 0.0f;
            lsum += p0 + p1;
            __nv_bfloat16 h0, l0, h1, l1;
            split2(p0, h0, l0);
            split2(p1, h1, l1);
            pk[cb2][c2]     = ((uint32_t)__bfloat16_as_ushort(h1) << 16) | __bfloat16_as_ushort(h0);
            pk[2 + cb2][c2] = ((uint32_t)__bfloat16_as_ushort(l1) << 16) | __bfloat16_as_ushort(l0);
        }
    }
    __syncthreads();   // ALL S reads complete before any P overwrite
    uint32_t woff = (uint32_t)sub << 21;
    TCGEN05_ST_X16(region + wg * 32 + 0  + woff, pk[0]);
    TCGEN05_ST_X16(region + wg * 32 + 16 + woff, pk[1]);
    TCGEN05_ST_X16(region + 64 + wg * 32 + 0  + woff, pk[2]);
    TCGEN05_ST_X16(region + 64 + wg * 32 + 16 + woff, pk[3]);
    TCGEN05_WAIT_ST();
    TCGEN05_FENCE_BEFORE();
    __syncthreads();
}

// epilogue store for one tile
__device__ __forceinline__ void attn_store(uint32_t tO, int wg, float inv,
                                           int b, int h, int qrow)
{
    uint32_t od[32];
    TCGEN05_LD_X32(od, tO + wg * 32);
    TCGEN05_WAIT_LD();
    size_t ob = ((size_t)b * Sdim + qrow) * (Hdim * Ddim) + h * Ddim + wg * 32;
    #pragma unroll
    for (int g4 = 0; g4 < 8; g4++) {
        float v0 = __uint_as_float(od[g4 * 4 + 0]) * inv;
        float v1 = __uint_as_float(od[g4 * 4 + 1]) * inv;
        float v2 = __uint_as_float(od[g4 * 4 + 2]) * inv;
        float v3 = __uint_as_float(od[g4 * 4 + 3]) * inv;
        __nv_bfloat16 h0, h1, h2, h3, l0, l1, l2, l3;
        split2(v0, h0, l0); split2(v1, h1, l1);
        split2(v2, h2, l2); split2(v3, h3, l3);
        *(ushort4*)(g_ahi + ob + g4 * 4) = make_ushort4(
            __bfloat16_as_ushort(h0), __bfloat16_as_ushort(h1),
            __bfloat16_as_ushort(h2), __bfloat16_as_ushort(h3));
        *(ushort4*)(g_alo + ob + g4 * 4) = make_ushort4(
            __bfloat16_as_ushort(l0), __bfloat16_as_ushort(l1),
            __bfloat16_as_ushort(l2), __bfloat16_as_ushort(l3));
    }
}
#endif

// ---------------- kernel: dual-q-tile tcgen05 causal flash attention --------
// CTA handles q-tiles qA=2t (rows q0A..+127) and qB=2t+1, sharing K/V tiles.
// Tensor order per j: QK_A -> QK_B -> PV_A -> PV_B (in-order pipe); softmax_A
// overlaps QK_B, softmax_B overlaps PV_A. 4 mbarriers (1 commit+1 wait per
// iter each => no parity ABA). Tile A runs j=qB fully masked (uniform flow).
__global__ __launch_bounds__(256) void attn_tc()
{
#if HAS_TCGEN05
    extern __shared__ char smem[];
    const uint32_t su = smem_to_u32(smem);
    const int tid = threadIdx.x;
    const int wid = tid >> 5;
    const int lid = tid & 31;
    const int wg  = wid >> 2;
    const int sub = wid & 3;
    const int bh = blockIdx.y;
    const int qt2 = gridDim.x - 1 - blockIdx.x;   // heavy pairs first
    const int q0A = qt2 * 256;
    const int jmax = 2 * qt2 + 1;

    if (wid == 0) { TCGEN05_ALLOC(su + A_TMPTR, 512); TCGEN05_RELINQ(); }
    if (tid == 0) {
        MBARRIER_INIT(su + A_MB_QKA, 1);
        MBARRIER_INIT(su + A_MB_QKB, 1);
        MBARRIER_INIT(su + A_MB_PVA, 1);
        MBARRIER_INIT(su + A_MB_PVB, 1);
    }
    __syncthreads();
    uint32_t tmem;
    asm volatile("ld.shared.b32 %0, [%1];" : "=r"(tmem) : "r"(su + A_TMPTR));
    const uint32_t tSA = tmem;
    const uint32_t tSB = tmem + 128;
    const uint32_t tOA = tmem + 256;
    const uint32_t tOB = tmem + 320;

    // prologue: KV(0) via cp.async; QA+QB via plain ld/st
    attn_ld_kv(bh, 0, su + AKV_BASE, tid);
    #pragma unroll
    for (int u = 0; u < 8; u++) {
        int idx = tid + u * 256;                  // 2048 granules: 2 tiles x 128r x 8g
        int tile = idx >> 10;
        int r = (idx >> 3) & 127;
        int g = idx & 7;
        uint32_t sw = SMEM_SWIZZLE_128B((uint32_t)(r * 128 + g * 16));
        size_t qb = ((size_t)bh * Sdim + q0A + tile * 128 + r) * Ddim + g * 8;
        *(uint4*)(smem + AQ_BASE + tile * 32768 + sw)         = *(const uint4*)(g_qhi + qb);
        *(uint4*)(smem + AQ_BASE + tile * 32768 + 16384 + sw) = *(const uint4*)(g_qlo + qb);
    }
    CPA_WAIT(0);
    FENCE_PROXY_ASYNC();
    __syncthreads();

    const uint64_t dQAh = MAKE_SMEM_DESC(su + AQ_BASE);
    const uint64_t dQAl = MAKE_SMEM_DESC(su + AQ_BASE + 16384);
    const uint64_t dQBh = MAKE_SMEM_DESC(su + AQ_BASE + 32768);
    const uint64_t dQBl = MAKE_SMEM_DESC(su + AQ_BASE + 49152);

    if (wid == 0 && elect_one_pred())
        issue_qk(tSA, dQAh, dQAl, su + AKV_BASE, su + A_MB_QKA);   // QK_A(0)

    const int qrowA = q0A + sub * 32 + lid;
    const int qrowB = qrowA + 128;
    float lsumA = 0.0f, lsumB = 0.0f;

    for (int j = 0; j <= jmax; j++) {
        const uint32_t sb = su + AKV_BASE + (uint32_t)(j & 1) * AKV_SZ;
        const int j0 = j * 128;

        // free up stage (j+1)&1 (held KV(j-1)): PV_A/PV_B(j-1) must be done
        if (j > 0) {
            MBARRIER_WAIT_PARITY(su + A_MB_PVA, (j - 1) & 1);
            MBARRIER_WAIT_PARITY(su + A_MB_PVB, (j - 1) & 1);
        }
        if (j + 1 <= jmax)
            attn_ld_kv(bh, (j + 1) * 128, su + AKV_BASE + (uint32_t)((j + 1) & 1) * AKV_SZ, tid);

        // QK_A(j) done -> issue QK_B(j); softmax_A overlaps QK_B on tensor
        MBARRIER_WAIT_PARITY(su + A_MB_QKA, j & 1);
        if (wid == 0 && elect_one_pred())
            issue_qk(tSB, dQBh, dQBl, sb, su + A_MB_QKB);

        softmax_tile(tSA, j0, qrowA, wg, sub, lsumA);
        if (wid == 0 && elect_one_pred()) {
            TCGEN05_FENCE_AFTER();
            issue_pv(tOA, tSA, sb, j == 0, su + A_MB_PVA);
        }

        MBARRIER_WAIT_PARITY(su + A_MB_QKB, j & 1);
        softmax_tile(tSB, j0, qrowB, wg, sub, lsumB);
        if (wid == 0 && elect_one_pred()) {
            TCGEN05_FENCE_AFTER();
            issue_pv(tOB, tSB, sb, j == 0, su + A_MB_PVB);
        }

        // KV(j+1) landed -> issue QK_A(j+1) (after PV_A(j) in pipe order,
        // so the SA overwrite is safe on the in-order tensor queue)
        if (j + 1 <= jmax) {
            CPA_WAIT(0);
            FENCE_PROXY_ASYNC();
            __syncthreads();
            if (wid == 0 && elect_one_pred())
                issue_qk(tSA, dQAh, dQAl,
                         su + AKV_BASE + (uint32_t)((j + 1) & 1) * AKV_SZ, su + A_MB_QKA);
        }
    }

    MBARRIER_WAIT_PARITY(su + A_MB_PVA, jmax & 1);
    MBARRIER_WAIT_PARITY(su + A_MB_PVB, jmax & 1);
    TCGEN05_FENCE_AFTER();

    // cross-warpgroup lsum exchange (partner wg holds the other 64 columns)
    __syncthreads();
    ((float*)smem)[tid]       = lsumA;
    ((float*)smem)[256 + tid] = lsumB;
    __syncthreads();
    const float invA = 1.0f / (lsumA + ((float*)smem)[tid ^ 128]);
    const float invB = 1.0f / (lsumB + ((float*)smem)[256 + (tid ^ 128)]);

    const int b = bh >> 4;
    const int h = bh & 15;
    attn_store(tOA, wg, invA, b, h, qrowA);
    attn_store(tOB, wg, invB, b, h, qrowB);

    __syncthreads();
    if (wid == 0) TCGEN05_DEALLOC(tmem, 512);
#else
    // SIMT fallback (never runs on GB300; correct if loaded)
    const int tid = threadIdx.x;
    const int bh = blockIdx.y;
    const int qt2 = gridDim.x - 1 - blockIdx.x;
    const int qrow = qt2 * 256 + tid;
    float q[Ddim], o[Ddim];
    for (int d = 0; d < Ddim; d++) {
        size_t qi = ((size_t)bh * Sdim + qrow) * Ddim + d;
        q[d] = __bfloat162float(g_qhi[qi]) + __bfloat162float(g_qlo[qi]);
        o[d] = 0.0f;
    }
    float l = 0.0f;
    for (int key = 0; key <= qrow; key++) {
        float s = 0.0f;
        size_t kb = ((size_t)bh * Sdim + key) * Ddim;
        for (int d = 0; d < Ddim; d++)
            s += q[d] * (__bfloat162float(g_khi[kb + d]) + __bfloat162float(g_klo[kb + d]));
        float p = __expf(s * 0.125f);
        l += p;
        for (int d = 0; d < Ddim; d++) {
            size_t vi = ((size_t)bh * Ddim + d) * Sdim + key;
            o[d] += p * (__bfloat162float(g_vThi[vi]) + __bfloat162float(g_vTlo[vi]));
        }
    }
    const float inv = 1.0f / l;
    const int b = bh >> 4, h = bh & 15;
    size_t ob = ((size_t)b * Sdim + qrow) * (Hdim * Ddim) + h * Ddim;
    for (int d = 0; d < Ddim; d++) {
        __nv_bfloat16 hv, lv;
        split2(o[d] * inv, hv, lv);
        g_ahi[ob + d] = hv;
        g_alo[ob + d] = lv;
    }
#endif
}

// ---------------- kernel: output projection + bias (tile 128m x 256n) ------
__global__ __launch_bounds__(128) void proj_tc(
    const float* __restrict__ bias, float* __restrict__ out)
{
    extern __shared__ char smem[];
    const int tid = threadIdx.x;
    const int n0 = blockIdx.x * 256;
    const int m0 = blockIdx.y * 128;

#if HAS_TCGEN05
    const uint32_t su = smem_to_u32(smem);
    const int wid = tid >> 5;

    if (wid == 0) { TCGEN05_ALLOC(su + G_TMPTR, 256); TCGEN05_RELINQ(); }
    if (tid == 0) {
        MBARRIER_INIT(su + G_MBAR_L, 3);
        MBARRIER_INIT(su + G_MBAR_M, 1);
        MBARRIER_INIT(su + G_MBAR_F, 1);
    }
    __syncthreads();
    uint32_t tmem;
    asm volatile("ld.shared.b32 %0, [%1];" : "=r"(tmem) : "r"(su + G_TMPTR));

    tc_mainloop(g_ahi, g_alo, g_wp_hi, g_wp_lo, m0, n0, su, tmem, tid, wid);

    TCGEN05_FENCE_AFTER();
    epi_to_smem(smem, tmem, tid);

    const int cl = tid & 7;
    const int rr = tid >> 3;
    #pragma unroll
    for (int rep = 0; rep < 8; rep++) {
        int m = rr + rep * 16;
        int mg = m0 + m;
        #pragma unroll
        for (int q = 0; q < 8; q++) {
            int c = (cl + q * 8) * 4;
            float4 bv = *(const float4*)&bias[n0 + c];
            float4 v;
            v.x = *(const float*)(smem + (((size_t)(c + 0) * EPI_STRIDE + m) << 2)) + bv.x;
            v.y = *(const float*)(smem + (((size_t)(c + 1) * EPI_STRIDE + m) << 2)) + bv.y;
            v.z = *(const float*)(smem + (((size_t)(c + 2) * EPI_STRIDE + m) << 2)) + bv.z;
            v.w = *(const float*)(smem + (((size_t)(c + 3) * EPI_STRIDE + m) << 2)) + bv.w;
            *(float4*)&out[(size_t)mg * Edim + n0 + c] = v;
        }
    }

    __syncthreads();
    if (wid == 0) TCGEN05_DEALLOC(tmem, 256);
#else
    (void)smem;
    const int m = m0 + tid;
    for (int nc = 0; nc < 256; nc++) {
        const int n = n0 + nc;
        float s = bias[n];
        for (int k = 0; k < KDIM; k++) {
            float a = __bfloat162float(g_ahi[(size_t)m * KDIM + k]) +
                      __bfloat162float(g_alo[(size_t)m * KDIM + k]);
            s += a * (__bfloat162float(g_wp_hi[(size_t)n * KDIM + k]) +
                      __bfloat162float(g_wp_lo[(size_t)n * KDIM + k]));
        }
        out[(size_t)m * Edim + n] = s;
    }
#endif
}

// ---------------------------------------------------------------------------
extern "C" void kernel_launch(void* const* d_in, const int* in_sizes, int n_in,
                              void* d_out, int out_size)
{
    (void)in_sizes; (void)n_in; (void)out_size;
    const float* x     = (const float*)d_in[0];
    const float* Wq    = (const float*)d_in[1];
    const float* Wk    = (const float*)d_in[2];
    const float* Wv    = (const float*)d_in[3];
    const float* Wproj = (const float*)d_in[4];
    const float* bproj = (const float*)d_in[5];
    float* out = (float*)d_out;

    cudaFuncSetAttribute(qkv_tc,  cudaFuncAttributeMaxDynamicSharedMemorySize, G_SMEM_BYTES);
    cudaFuncSetAttribute(proj_tc, cudaFuncAttributeMaxDynamicSharedMemorySize, G_SMEM_BYTES);
    cudaFuncSetAttribute(attn_tc, cudaFuncAttributeMaxDynamicSharedMemorySize, A_SMEM_BYTES);

    __nv_bfloat16 *xhi, *xlo;
    cudaGetSymbolAddress((void**)&xhi, g_xhi);
    cudaGetSymbolAddress((void**)&xlo, g_xlo);

    const int n4 = Mrows * KDIM / 4;
    conv_split<<<(n4 + 255) / 256, 256>>>(x, xhi, xlo, n4);
    conv_wt<<<dim3(16, 16, 3), 256>>>(Wq, Wk, Wv);
    conv_wp<<<dim3(16, 16), 256>>>(Wproj);

    qkv_tc<<<dim3(QKVN / 256, Mrows / 128), 128, G_SMEM_BYTES>>>();
    attn_tc<<<dim3(Sdim / 256, BHdim), 256, A_SMEM_BYTES>>>();
    proj_tc<<<dim3(Edim / 256, Mrows / 128), 128, G_SMEM_BYTES>>>(bproj, out);
}